// round 1
// baseline (speedup 1.0000x reference)
#include <cuda_runtime.h>
#include <math.h>

// Shapes are fixed by the benchmark: B=4, T=4096, D=1024, SEG=64.
#define M_LOC   16384          // B*T rows
#define M_GLB   256            // B*NSEG rows
#define DIM     1024
#define QKVDIM  3072

// ---------------- scratch (static device globals; no allocation) ------------
__device__ float g_qkv_l[(size_t)M_LOC * QKVDIM];   // 192 MB
__device__ float g_lattn[(size_t)M_LOC * DIM];      // 64 MB
__device__ float g_means[(size_t)M_GLB * DIM];
__device__ float g_qkv_g[(size_t)M_GLB * QKVDIM];
__device__ float g_gattn[(size_t)M_GLB * DIM];
__device__ float g_glob [(size_t)M_GLB * DIM];

// ---------------- segment means: means[b*64+g][d] = mean over 64 tokens -----
__global__ void __launch_bounds__(256) means_kernel(const float* __restrict__ x,
                                                    float* __restrict__ means) {
    const int sb = blockIdx.x;                 // 0..255 == b*64+g
    const int d = threadIdx.x * 4;             // 256 threads * 4 = 1024
    const float* xp = x + (size_t)sb * 64 * DIM;
    float4 acc = make_float4(0.f, 0.f, 0.f, 0.f);
    #pragma unroll 8
    for (int s = 0; s < 64; s++) {
        float4 v = *(const float4*)(xp + (size_t)s * DIM + d);
        acc.x += v.x; acc.y += v.y; acc.z += v.z; acc.w += v.w;
    }
    const float inv = 1.0f / 64.0f;
    float4 r = make_float4(acc.x * inv, acc.y * inv, acc.z * inv, acc.w * inv);
    *(float4*)(means + (size_t)sb * DIM + d) = r;
}

// ---------------- NT GEMM: C[M,N] = A[M,K] @ W[N,K]^T + bias[N] (+extra) ----
// BM=BN=64, BK=16, 256 threads, 4x4 per thread.
// If extra != nullptr: C[m][n] += extra[m>>6][n]  (global-attn broadcast add).
__global__ void __launch_bounds__(256) gemm_nt_kernel(
    const float* __restrict__ A, const float* __restrict__ W,
    const float* __restrict__ bias, const float* __restrict__ extra,
    float* __restrict__ C, int M, int N, int K)
{
    __shared__ float As[16][64];
    __shared__ float Bs[16][64];

    const int tid = threadIdx.x;
    const int tx = tid & 15, ty = tid >> 4;
    const int m0 = blockIdx.y * 64, n0 = blockIdx.x * 64;

    const int lr = tid >> 2;          // 0..63 row within tile
    const int lk = (tid & 3) * 4;     // 0,4,8,12 (float4 k-offset)
    const float* Ap = A + (size_t)(m0 + lr) * K + lk;
    const float* Wp = W + (size_t)(n0 + lr) * K + lk;

    float acc[4][4] = {};

    for (int k0 = 0; k0 < K; k0 += 16) {
        float4 a4 = *(const float4*)(Ap + k0);
        float4 w4 = *(const float4*)(Wp + k0);
        As[lk + 0][lr] = a4.x; As[lk + 1][lr] = a4.y;
        As[lk + 2][lr] = a4.z; As[lk + 3][lr] = a4.w;
        Bs[lk + 0][lr] = w4.x; Bs[lk + 1][lr] = w4.y;
        Bs[lk + 2][lr] = w4.z; Bs[lk + 3][lr] = w4.w;
        __syncthreads();
        #pragma unroll
        for (int kk = 0; kk < 16; kk++) {
            float4 av = *(const float4*)&As[kk][ty * 4];
            float4 bv = *(const float4*)&Bs[kk][tx * 4];
            float a[4] = {av.x, av.y, av.z, av.w};
            float b[4] = {bv.x, bv.y, bv.z, bv.w};
            #pragma unroll
            for (int i = 0; i < 4; i++)
                #pragma unroll
                for (int j = 0; j < 4; j++)
                    acc[i][j] += a[i] * b[j];
        }
        __syncthreads();
    }

    #pragma unroll
    for (int i = 0; i < 4; i++) {
        const int m = m0 + ty * 4 + i;
        const float* ex = extra ? (extra + (size_t)(m >> 6) * N) : nullptr;
        #pragma unroll
        for (int j = 0; j < 4; j++) {
            const int n = n0 + tx * 4 + j;
            float v = acc[i][j] + bias[n];
            if (ex) v += ex[n];
            C[(size_t)m * N + n] = v;
        }
    }
}

// ---------------- segment attention (S=64), one block per (sequence, head) --
// qkv rows: token index = seq*64 + s, row stride 3*D; q at h*HD, k at D+h*HD,
// v at 2D+h*HD. out rows stride D, written at h*HD.
template <int HD, int NH>
__global__ void __launch_bounds__(256) attn_kernel(const float* __restrict__ qkv,
                                                   float* __restrict__ out) {
    constexpr int D  = NH * HD;
    constexpr int RS = 3 * D;        // qkv row stride
    constexpr int PS = HD + 1;       // padded smem stride (bank-conflict-free)
    constexpr int SP = 65;           // score row stride
    constexpr int TC = HD / 16;      // output cols per thread

    extern __shared__ float sm[];
    float* Qs = sm;                  // 64*PS
    float* Ks = sm + 64 * PS;        // 64*PS  (reused for V)
    float* Ss = sm + 2 * 64 * PS;    // 64*SP

    const int tid = threadIdx.x;
    const int tx = tid & 15, ty = tid >> 4;
    const int seq = blockIdx.x;
    const int h = blockIdx.y;
    const float* base = qkv + (size_t)seq * 64 * RS;
    const int qoff = h * HD;
    const int koff = D + h * HD;
    const int voff = 2 * D + h * HD;

    // load Q, K tiles
    for (int idx = tid * 4; idx < 64 * HD; idx += 1024) {
        const int s = idx / HD, d = idx - s * HD;
        const float* rp = base + (size_t)s * RS;
        float4 q4 = *(const float4*)(rp + qoff + d);
        float4 k4 = *(const float4*)(rp + koff + d);
        float* qd = &Qs[s * PS + d];
        qd[0] = q4.x; qd[1] = q4.y; qd[2] = q4.z; qd[3] = q4.w;
        float* kd = &Ks[s * PS + d];
        kd[0] = k4.x; kd[1] = k4.y; kd[2] = k4.z; kd[3] = k4.w;
    }
    __syncthreads();

    // scores: 4x4 per thread, register accumulate
    float acc[4][4] = {};
    #pragma unroll 4
    for (int k = 0; k < HD; k++) {
        float a[4], b[4];
        #pragma unroll
        for (int i = 0; i < 4; i++) a[i] = Qs[(ty * 4 + i) * PS + k];
        #pragma unroll
        for (int j = 0; j < 4; j++) b[j] = Ks[(tx * 4 + j) * PS + k];
        #pragma unroll
        for (int i = 0; i < 4; i++)
            #pragma unroll
            for (int j = 0; j < 4; j++)
                acc[i][j] += a[i] * b[j];
    }
    const float scale = rsqrtf((float)HD);
    #pragma unroll
    for (int i = 0; i < 4; i++)
        #pragma unroll
        for (int j = 0; j < 4; j++)
            Ss[(ty * 4 + i) * SP + tx * 4 + j] = acc[i][j] * scale;
    __syncthreads();

    // softmax: one thread per row
    if (tid < 64) {
        float* row = &Ss[tid * SP];
        float mx = -1e30f;
        for (int j = 0; j < 64; j++) mx = fmaxf(mx, row[j]);
        float sum = 0.f;
        for (int j = 0; j < 64; j++) { float e = expf(row[j] - mx); row[j] = e; sum += e; }
        const float inv = 1.0f / sum;
        for (int j = 0; j < 64; j++) row[j] *= inv;
    }
    __syncthreads();

    // load V into Ks (safe: all K reads finished before softmax barrier)
    for (int idx = tid * 4; idx < 64 * HD; idx += 1024) {
        const int s = idx / HD, d = idx - s * HD;
        float4 v4 = *(const float4*)(base + (size_t)s * RS + voff + d);
        float* kd = &Ks[s * PS + d];
        kd[0] = v4.x; kd[1] = v4.y; kd[2] = v4.z; kd[3] = v4.w;
    }
    __syncthreads();

    // P @ V: 4 rows x TC cols per thread
    float acc2[4][TC] = {};
    for (int j = 0; j < 64; j++) {
        float p[4];
        #pragma unroll
        for (int i = 0; i < 4; i++) p[i] = Ss[(ty * 4 + i) * SP + j];
        #pragma unroll
        for (int c = 0; c < TC; c++) {
            const float v = Ks[j * PS + tx * TC + c];
            #pragma unroll
            for (int i = 0; i < 4; i++) acc2[i][c] += p[i] * v;
        }
    }
    #pragma unroll
    for (int i = 0; i < 4; i++) {
        float* op = out + (size_t)(seq * 64 + ty * 4 + i) * D + h * HD + tx * TC;
        #pragma unroll
        for (int c = 0; c < TC; c++) op[c] = acc2[i][c];
    }
}

// smem sizes for the two instantiations
static const int SMEM_L = (2 * 64 * 129 + 64 * 65) * sizeof(float);  // 82,688 B
static const int SMEM_G = (2 * 64 * 257 + 64 * 65) * sizeof(float);  // 148,224 B

extern "C" void kernel_launch(void* const* d_in, const int* in_sizes, int n_in,
                              void* d_out, int out_size) {
    const float* x       = (const float*)d_in[0];
    const float* w_in_l  = (const float*)d_in[1];
    const float* b_in_l  = (const float*)d_in[2];
    const float* w_out_l = (const float*)d_in[3];
    const float* b_out_l = (const float*)d_in[4];
    const float* w_in_g  = (const float*)d_in[5];
    const float* b_in_g  = (const float*)d_in[6];
    const float* w_out_g = (const float*)d_in[7];
    const float* b_out_g = (const float*)d_in[8];
    float* out = (float*)d_out;

    float *qkv_l, *lattn, *means, *qkv_g, *gattn, *glob;
    cudaGetSymbolAddress((void**)&qkv_l, g_qkv_l);
    cudaGetSymbolAddress((void**)&lattn, g_lattn);
    cudaGetSymbolAddress((void**)&means, g_means);
    cudaGetSymbolAddress((void**)&qkv_g, g_qkv_g);
    cudaGetSymbolAddress((void**)&gattn, g_gattn);
    cudaGetSymbolAddress((void**)&glob,  g_glob);

    cudaFuncSetAttribute((const void*)attn_kernel<128, 8>,
                         cudaFuncAttributeMaxDynamicSharedMemorySize, SMEM_L);
    cudaFuncSetAttribute((const void*)attn_kernel<256, 4>,
                         cudaFuncAttributeMaxDynamicSharedMemorySize, SMEM_G);

    // ---- global path (tiny) ----
    means_kernel<<<M_GLB, 256>>>(x, means);
    gemm_nt_kernel<<<dim3(QKVDIM / 64, M_GLB / 64), 256>>>(
        means, w_in_g, b_in_g, nullptr, qkv_g, M_GLB, QKVDIM, DIM);
    attn_kernel<256, 4><<<dim3(4, 4), 256, SMEM_G>>>(qkv_g, gattn);
    gemm_nt_kernel<<<dim3(DIM / 64, M_GLB / 64), 256>>>(
        gattn, w_out_g, b_out_g, nullptr, glob, M_GLB, DIM, DIM);

    // ---- local path (bulk of the FLOPs) ----
    gemm_nt_kernel<<<dim3(QKVDIM / 64, M_LOC / 64), 256>>>(
        x, w_in_l, b_in_l, nullptr, qkv_l, M_LOC, QKVDIM, DIM);
    attn_kernel<128, 8><<<dim3(M_GLB, 8), 256, SMEM_L>>>(qkv_l, lattn);
    // fused: out-proj + bias + broadcast global add
    gemm_nt_kernel<<<dim3(DIM / 64, M_LOC / 64), 256>>>(
        lattn, w_out_l, b_out_l, glob, out, M_LOC, DIM, DIM);
}

// round 2
// speedup vs baseline: 2.9310x; 2.9310x over previous
#include <cuda_runtime.h>
#include <math.h>

// Shapes fixed by the benchmark: B=4, T=4096, D=1024, SEG=64.
#define M_LOC   16384
#define M_GLB   256
#define DIM     1024
#define QKVDIM  3072

// ---------------- scratch ---------------------------------------------------
__device__ float g_qkv_l[(size_t)M_LOC * QKVDIM];
__device__ float g_lattn[(size_t)M_LOC * DIM];
__device__ float g_means[(size_t)M_GLB * DIM];
__device__ float g_qkv_g[(size_t)M_GLB * QKVDIM];
__device__ float g_gattn[(size_t)M_GLB * DIM];
__device__ float g_glob [(size_t)M_GLB * DIM];

// ---------------- segment means ---------------------------------------------
__global__ void __launch_bounds__(256) means_kernel(const float* __restrict__ x,
                                                    float* __restrict__ means) {
    const int sb = blockIdx.x;
    const int d = threadIdx.x * 4;
    const float* xp = x + (size_t)sb * 64 * DIM;
    float4 acc = make_float4(0.f, 0.f, 0.f, 0.f);
    #pragma unroll 8
    for (int s = 0; s < 64; s++) {
        float4 v = *(const float4*)(xp + (size_t)s * DIM + d);
        acc.x += v.x; acc.y += v.y; acc.z += v.z; acc.w += v.w;
    }
    const float inv = 1.0f / 64.0f;
    *(float4*)(means + (size_t)sb * DIM + d) =
        make_float4(acc.x * inv, acc.y * inv, acc.z * inv, acc.w * inv);
}

// ---------------- TF32 tensor-core NT GEMM ----------------------------------
// C[M,N] = A[M,K] @ W[N,K]^T + bias[N] (+ extra[m>>6][N] if extra != null)
// BM=BN=128, BK=16, 256 threads, 8 warps (4 x 2), warp tile 32x64,
// mma.sync.m16n8k8 tf32, fp32 accumulate. Double-buffered smem, reg prefetch.
#define BM 128
#define BN 128
#define BK 16
#define BKP 20   // padded k-stride: bank=(20*g+r)%32 injective -> conflict-free

__device__ __forceinline__ unsigned f2tf(float f) {
    unsigned r;
    asm("cvt.rna.tf32.f32 %0, %1;" : "=r"(r) : "f"(f));
    return r;
}

__device__ __forceinline__ void mma_tf32(float c[4], const unsigned a[4],
                                         const unsigned b[2]) {
    asm volatile(
        "mma.sync.aligned.m16n8k8.row.col.f32.tf32.tf32.f32 "
        "{%0,%1,%2,%3}, {%4,%5,%6,%7}, {%8,%9}, {%0,%1,%2,%3};"
        : "+f"(c[0]), "+f"(c[1]), "+f"(c[2]), "+f"(c[3])
        : "r"(a[0]), "r"(a[1]), "r"(a[2]), "r"(a[3]), "r"(b[0]), "r"(b[1]));
}

__global__ void __launch_bounds__(256) gemm_tc_kernel(
    const float* __restrict__ A, const float* __restrict__ W,
    const float* __restrict__ bias, const float* __restrict__ extra,
    float* __restrict__ C, int M, int N, int K)
{
    __shared__ unsigned As[2][BM][BKP];
    __shared__ unsigned Ws[2][BN][BKP];

    const int tid  = threadIdx.x;
    const int lane = tid & 31;
    const int warp = tid >> 5;
    const int wm = warp >> 1;          // 0..3
    const int wn = warp & 1;           // 0..1
    const int gID = lane >> 2;         // 0..7
    const int tig = lane & 3;          // 0..3
    const int m0 = blockIdx.y * BM, n0 = blockIdx.x * BN;

    // global load mapping: 2 float4 per tensor per thread per BK-iter
    const int r0 = tid >> 2;           // 0..63
    const int kq = (tid & 3) * 4;      // 0,4,8,12
    const float* Ap0 = A + (size_t)(m0 + r0) * K + kq;
    const float* Ap1 = A + (size_t)(m0 + r0 + 64) * K + kq;
    const float* Wp0 = W + (size_t)(n0 + r0) * K + kq;
    const float* Wp1 = W + (size_t)(n0 + r0 + 64) * K + kq;

    float acc[2][8][4];
    #pragma unroll
    for (int i = 0; i < 2; i++)
        #pragma unroll
        for (int j = 0; j < 8; j++)
            #pragma unroll
            for (int c = 0; c < 4; c++) acc[i][j][c] = 0.f;

    // prologue: load first tiles
    float4 a0 = *(const float4*)Ap0;
    float4 a1 = *(const float4*)Ap1;
    float4 w0 = *(const float4*)Wp0;
    float4 w1 = *(const float4*)Wp1;

    *(uint4*)&As[0][r0][kq]      = make_uint4(f2tf(a0.x), f2tf(a0.y), f2tf(a0.z), f2tf(a0.w));
    *(uint4*)&As[0][r0 + 64][kq] = make_uint4(f2tf(a1.x), f2tf(a1.y), f2tf(a1.z), f2tf(a1.w));
    *(uint4*)&Ws[0][r0][kq]      = make_uint4(f2tf(w0.x), f2tf(w0.y), f2tf(w0.z), f2tf(w0.w));
    *(uint4*)&Ws[0][r0 + 64][kq] = make_uint4(f2tf(w1.x), f2tf(w1.y), f2tf(w1.z), f2tf(w1.w));
    __syncthreads();

    int buf = 0;
    for (int k0 = BK; k0 <= K; k0 += BK) {
        const bool more = (k0 < K);
        // async prefetch of next tile into registers (latency hidden by mma)
        if (more) {
            a0 = *(const float4*)(Ap0 + k0);
            a1 = *(const float4*)(Ap1 + k0);
            w0 = *(const float4*)(Wp0 + k0);
            w1 = *(const float4*)(Wp1 + k0);
        }

        // compute on buf
        #pragma unroll
        for (int ks = 0; ks < 2; ks++) {
            const int kb = ks * 8;
            unsigned af[2][4], bf[8][2];
            #pragma unroll
            for (int mi = 0; mi < 2; mi++) {
                const int row = wm * 32 + mi * 16 + gID;
                af[mi][0] = As[buf][row][kb + tig];
                af[mi][1] = As[buf][row + 8][kb + tig];
                af[mi][2] = As[buf][row][kb + tig + 4];
                af[mi][3] = As[buf][row + 8][kb + tig + 4];
            }
            #pragma unroll
            for (int nj = 0; nj < 8; nj++) {
                const int col = wn * 64 + nj * 8 + gID;
                bf[nj][0] = Ws[buf][col][kb + tig];
                bf[nj][1] = Ws[buf][col][kb + tig + 4];
            }
            #pragma unroll
            for (int mi = 0; mi < 2; mi++)
                #pragma unroll
                for (int nj = 0; nj < 8; nj++)
                    mma_tf32(acc[mi][nj], af[mi], bf[nj]);
        }

        if (more) {
            const int nb = buf ^ 1;
            *(uint4*)&As[nb][r0][kq]      = make_uint4(f2tf(a0.x), f2tf(a0.y), f2tf(a0.z), f2tf(a0.w));
            *(uint4*)&As[nb][r0 + 64][kq] = make_uint4(f2tf(a1.x), f2tf(a1.y), f2tf(a1.z), f2tf(a1.w));
            *(uint4*)&Ws[nb][r0][kq]      = make_uint4(f2tf(w0.x), f2tf(w0.y), f2tf(w0.z), f2tf(w0.w));
            *(uint4*)&Ws[nb][r0 + 64][kq] = make_uint4(f2tf(w1.x), f2tf(w1.y), f2tf(w1.z), f2tf(w1.w));
            __syncthreads();
            buf = nb;
        }
    }

    // epilogue: bias + optional broadcast add, float2 stores
    #pragma unroll
    for (int mi = 0; mi < 2; mi++) {
        #pragma unroll
        for (int nj = 0; nj < 8; nj++) {
            const int col = n0 + wn * 64 + nj * 8 + tig * 2;
            const float b0 = bias[col], b1 = bias[col + 1];
            #pragma unroll
            for (int h = 0; h < 2; h++) {
                const int row = m0 + wm * 32 + mi * 16 + gID + h * 8;
                float v0 = acc[mi][nj][h * 2 + 0] + b0;
                float v1 = acc[mi][nj][h * 2 + 1] + b1;
                if (extra) {
                    const float* ex = extra + (size_t)(row >> 6) * N;
                    v0 += ex[col]; v1 += ex[col + 1];
                }
                *(float2*)&C[(size_t)row * N + col] = make_float2(v0, v1);
            }
        }
    }
}

// ---------------- segment attention (S=64) ----------------------------------
template <int HD, int NH>
__global__ void __launch_bounds__(256) attn_kernel(const float* __restrict__ qkv,
                                                   float* __restrict__ out) {
    constexpr int D  = NH * HD;
    constexpr int RS = 3 * D;
    constexpr int PS = HD + 1;
    constexpr int SP = 65;
    constexpr int TC = HD / 16;

    extern __shared__ float sm[];
    float* Qs = sm;
    float* Ks = sm + 64 * PS;
    float* Ss = sm + 2 * 64 * PS;

    const int tid = threadIdx.x;
    const int tx = tid & 15, ty = tid >> 4;
    const int seq = blockIdx.x;
    const int h = blockIdx.y;
    const float* base = qkv + (size_t)seq * 64 * RS;
    const int qoff = h * HD;
    const int koff = D + h * HD;
    const int voff = 2 * D + h * HD;

    for (int idx = tid * 4; idx < 64 * HD; idx += 1024) {
        const int s = idx / HD, d = idx - s * HD;
        const float* rp = base + (size_t)s * RS;
        float4 q4 = *(const float4*)(rp + qoff + d);
        float4 k4 = *(const float4*)(rp + koff + d);
        float* qd = &Qs[s * PS + d];
        qd[0] = q4.x; qd[1] = q4.y; qd[2] = q4.z; qd[3] = q4.w;
        float* kd = &Ks[s * PS + d];
        kd[0] = k4.x; kd[1] = k4.y; kd[2] = k4.z; kd[3] = k4.w;
    }
    __syncthreads();

    float acc[4][4] = {};
    #pragma unroll 4
    for (int k = 0; k < HD; k++) {
        float a[4], b[4];
        #pragma unroll
        for (int i = 0; i < 4; i++) a[i] = Qs[(ty * 4 + i) * PS + k];
        #pragma unroll
        for (int j = 0; j < 4; j++) b[j] = Ks[(tx * 4 + j) * PS + k];
        #pragma unroll
        for (int i = 0; i < 4; i++)
            #pragma unroll
            for (int j = 0; j < 4; j++)
                acc[i][j] += a[i] * b[j];
    }
    const float scale = rsqrtf((float)HD);
    #pragma unroll
    for (int i = 0; i < 4; i++)
        #pragma unroll
        for (int j = 0; j < 4; j++)
            Ss[(ty * 4 + i) * SP + tx * 4 + j] = acc[i][j] * scale;
    __syncthreads();

    if (tid < 64) {
        float* row = &Ss[tid * SP];
        float mx = -1e30f;
        for (int j = 0; j < 64; j++) mx = fmaxf(mx, row[j]);
        float sum = 0.f;
        for (int j = 0; j < 64; j++) { float e = expf(row[j] - mx); row[j] = e; sum += e; }
        const float inv = 1.0f / sum;
        for (int j = 0; j < 64; j++) row[j] *= inv;
    }
    __syncthreads();

    for (int idx = tid * 4; idx < 64 * HD; idx += 1024) {
        const int s = idx / HD, d = idx - s * HD;
        float4 v4 = *(const float4*)(base + (size_t)s * RS + voff + d);
        float* kd = &Ks[s * PS + d];
        kd[0] = v4.x; kd[1] = v4.y; kd[2] = v4.z; kd[3] = v4.w;
    }
    __syncthreads();

    float acc2[4][TC] = {};
    for (int j = 0; j < 64; j++) {
        float p[4];
        #pragma unroll
        for (int i = 0; i < 4; i++) p[i] = Ss[(ty * 4 + i) * SP + j];
        #pragma unroll
        for (int c = 0; c < TC; c++) {
            const float v = Ks[j * PS + tx * TC + c];
            #pragma unroll
            for (int i = 0; i < 4; i++) acc2[i][c] += p[i] * v;
        }
    }
    #pragma unroll
    for (int i = 0; i < 4; i++) {
        float* op = out + (size_t)(seq * 64 + ty * 4 + i) * D + h * HD + tx * TC;
        #pragma unroll
        for (int c = 0; c < TC; c++) op[c] = acc2[i][c];
    }
}

static const int SMEM_L = (2 * 64 * 129 + 64 * 65) * sizeof(float);
static const int SMEM_G = (2 * 64 * 257 + 64 * 65) * sizeof(float);

extern "C" void kernel_launch(void* const* d_in, const int* in_sizes, int n_in,
                              void* d_out, int out_size) {
    const float* x       = (const float*)d_in[0];
    const float* w_in_l  = (const float*)d_in[1];
    const float* b_in_l  = (const float*)d_in[2];
    const float* w_out_l = (const float*)d_in[3];
    const float* b_out_l = (const float*)d_in[4];
    const float* w_in_g  = (const float*)d_in[5];
    const float* b_in_g  = (const float*)d_in[6];
    const float* w_out_g = (const float*)d_in[7];
    const float* b_out_g = (const float*)d_in[8];
    float* out = (float*)d_out;

    float *qkv_l, *lattn, *means, *qkv_g, *gattn, *glob;
    cudaGetSymbolAddress((void**)&qkv_l, g_qkv_l);
    cudaGetSymbolAddress((void**)&lattn, g_lattn);
    cudaGetSymbolAddress((void**)&means, g_means);
    cudaGetSymbolAddress((void**)&qkv_g, g_qkv_g);
    cudaGetSymbolAddress((void**)&gattn, g_gattn);
    cudaGetSymbolAddress((void**)&glob,  g_glob);

    cudaFuncSetAttribute((const void*)attn_kernel<128, 8>,
                         cudaFuncAttributeMaxDynamicSharedMemorySize, SMEM_L);
    cudaFuncSetAttribute((const void*)attn_kernel<256, 4>,
                         cudaFuncAttributeMaxDynamicSharedMemorySize, SMEM_G);

    // ---- global path (tiny) ----
    means_kernel<<<M_GLB, 256>>>(x, means);
    gemm_tc_kernel<<<dim3(QKVDIM / BN, M_GLB / BM), 256>>>(
        means, w_in_g, b_in_g, nullptr, qkv_g, M_GLB, QKVDIM, DIM);
    attn_kernel<256, 4><<<dim3(4, 4), 256, SMEM_G>>>(qkv_g, gattn);
    gemm_tc_kernel<<<dim3(DIM / BN, M_GLB / BM), 256>>>(
        gattn, w_out_g, b_out_g, nullptr, glob, M_GLB, DIM, DIM);

    // ---- local path (bulk of FLOPs) ----
    gemm_tc_kernel<<<dim3(QKVDIM / BN, M_LOC / BM), 256>>>(
        x, w_in_l, b_in_l, nullptr, qkv_l, M_LOC, QKVDIM, DIM);
    attn_kernel<128, 8><<<dim3(M_GLB, 8), 256, SMEM_L>>>(qkv_l, lattn);
    gemm_tc_kernel<<<dim3(DIM / BN, M_LOC / BM), 256>>>(
        lattn, w_out_l, b_out_l, glob, out, M_LOC, DIM, DIM);
}

// round 5
// speedup vs baseline: 4.8898x; 1.6683x over previous
#include <cuda_runtime.h>
#include <cuda_fp16.h>
#include <math.h>
#include <cstdint>

// Shapes fixed by the benchmark: B=4, T=4096, D=1024, SEG=64.
#define M_LOC   16384
#define M_GLB   256
#define DIM     1024
#define QKVDIM  3072

// ---------------- scratch ---------------------------------------------------
__device__ __half g_xh    [(size_t)M_LOC * DIM];
__device__ __half g_w1l_h [(size_t)QKVDIM * DIM];
__device__ __half g_w2l_h [(size_t)DIM * DIM];
__device__ __half g_w1g_h [(size_t)QKVDIM * DIM];
__device__ __half g_w2g_h [(size_t)DIM * DIM];
__device__ float  g_qkv_l [(size_t)M_LOC * QKVDIM];
__device__ __half g_lattn [(size_t)M_LOC * DIM];
__device__ __half g_means [(size_t)M_GLB * DIM];
__device__ float  g_qkv_g [(size_t)M_GLB * QKVDIM];
__device__ __half g_gattn [(size_t)M_GLB * DIM];
__device__ float  g_glob  [(size_t)M_GLB * DIM];

// ---------------- fp32 -> fp16 conversion -----------------------------------
__global__ void __launch_bounds__(256) f2h_kernel(const float4* __restrict__ in,
                                                  __half2* __restrict__ out, int n4) {
    int i = blockIdx.x * blockDim.x + threadIdx.x;
    if (i < n4) {
        float4 v = in[i];
        out[2 * i]     = __floats2half2_rn(v.x, v.y);
        out[2 * i + 1] = __floats2half2_rn(v.z, v.w);
    }
}

// ---------------- segment means (fp16 output) -------------------------------
__global__ void __launch_bounds__(256) means_kernel(const float* __restrict__ x,
                                                    __half* __restrict__ means) {
    const int sb = blockIdx.x;
    const int d = threadIdx.x * 4;
    const float* xp = x + (size_t)sb * 64 * DIM;
    float4 acc = make_float4(0.f, 0.f, 0.f, 0.f);
    #pragma unroll 8
    for (int s = 0; s < 64; s++) {
        float4 v = *(const float4*)(xp + (size_t)s * DIM + d);
        acc.x += v.x; acc.y += v.y; acc.z += v.z; acc.w += v.w;
    }
    const float inv = 1.0f / 64.0f;
    __half2* mp = (__half2*)(means + (size_t)sb * DIM + d);
    mp[0] = __floats2half2_rn(acc.x * inv, acc.y * inv);
    mp[1] = __floats2half2_rn(acc.z * inv, acc.w * inv);
}

// ---------------- fp16 tensor-core NT GEMM ----------------------------------
// C[M,N] = A[M,K] @ W[N,K]^T + bias[N] (+ extra[m>>6][N] if extra != null)
// BM=BN=128, BK=32, 4-stage cp.async pipeline, 256 threads, 8 warps (4m x 2n),
// warp tile 32x64, mma.sync.m16n8k16.f16 with fp32 accumulate.
#define BM 128
#define BN 128
#define BK 32
#define SKP 40      // smem k-stride in halves: bank=(20*row+tig)%32 injective
#define STAGES 4
#define ATILE (BM * SKP)            // halves per stage per matrix
#define GEMM_DYN_SMEM (2 * STAGES * ATILE * 2)   // bytes (81920)

__device__ __forceinline__ uint32_t s2u(const void* p) {
    uint32_t a;
    asm("{.reg .u64 t; cvta.to.shared.u64 t, %1; cvt.u32.u64 %0, t;}" : "=r"(a) : "l"(p));
    return a;
}
__device__ __forceinline__ void cpa(uint32_t s, const void* g) {
    asm volatile("cp.async.cg.shared.global [%0], [%1], 16;" :: "r"(s), "l"(g));
}
__device__ __forceinline__ void mma_f16(float c[4], const uint32_t a[4],
                                        const uint32_t b[2]) {
    asm volatile(
        "mma.sync.aligned.m16n8k16.row.col.f32.f16.f16.f32 "
        "{%0,%1,%2,%3}, {%4,%5,%6,%7}, {%8,%9}, {%0,%1,%2,%3};"
        : "+f"(c[0]), "+f"(c[1]), "+f"(c[2]), "+f"(c[3])
        : "r"(a[0]), "r"(a[1]), "r"(a[2]), "r"(a[3]), "r"(b[0]), "r"(b[1]));
}

__global__ void __launch_bounds__(256) gemm_h(
    const __half* __restrict__ A, const __half* __restrict__ W,
    const float* __restrict__ bias, const float* __restrict__ extra,
    float* __restrict__ C, int M, int N, int K)
{
    extern __shared__ __align__(16) __half smh[];
    __half* As = smh;                        // [STAGES][BM][SKP]
    __half* Ws = smh + STAGES * ATILE;

    const int tid  = threadIdx.x;
    const int lane = tid & 31;
    const int warp = tid >> 5;
    const int wm = warp >> 1;              // 0..3
    const int wn = warp & 1;               // 0..1
    const int g   = lane >> 2;             // 0..7
    const int tig = lane & 3;              // 0..3
    const int m0 = blockIdx.y * BM;
    const int n0 = blockIdx.x * BN;

    float acc[2][8][4];
    #pragma unroll
    for (int i = 0; i < 2; i++)
        #pragma unroll
        for (int j = 0; j < 8; j++)
            #pragma unroll
            for (int c = 0; c < 4; c++) acc[i][j][c] = 0.f;

    const int nch = K / BK;

    auto load_chunk = [&](int c, int s) {
        const int k0 = c * BK;
        __half* Ab = As + s * ATILE;
        __half* Bb = Ws + s * ATILE;
        #pragma unroll
        for (int i = 0; i < 2; i++) {
            const int e = tid + i * 256;
            const int row = e >> 2, c8 = (e & 3) * 8;
            cpa(s2u(Ab + row * SKP + c8), A + (size_t)(m0 + row) * K + k0 + c8);
            cpa(s2u(Bb + row * SKP + c8), W + (size_t)(n0 + row) * K + k0 + c8);
        }
        asm volatile("cp.async.commit_group;" ::: "memory");
    };

    #pragma unroll
    for (int p = 0; p < STAGES - 1; p++) load_chunk(p, p);

    for (int c = 0; c < nch; c++) {
        asm volatile("cp.async.wait_group %0;" :: "n"(STAGES - 2) : "memory");
        __syncthreads();

        const int cn = c + STAGES - 1;
        if (cn < nch) load_chunk(cn, cn & (STAGES - 1));

        const __half* Ab = As + (c & (STAGES - 1)) * ATILE;
        const __half* Bb = Ws + (c & (STAGES - 1)) * ATILE;
        #pragma unroll
        for (int ks = 0; ks < 2; ks++) {
            const int kb = ks * 16 + tig * 2;
            uint32_t af[2][4], bf[8][2];
            #pragma unroll
            for (int mi = 0; mi < 2; mi++) {
                const int row = wm * 32 + mi * 16 + g;
                af[mi][0] = *(const uint32_t*)&Ab[row * SKP + kb];
                af[mi][1] = *(const uint32_t*)&Ab[(row + 8) * SKP + kb];
                af[mi][2] = *(const uint32_t*)&Ab[row * SKP + kb + 8];
                af[mi][3] = *(const uint32_t*)&Ab[(row + 8) * SKP + kb + 8];
            }
            #pragma unroll
            for (int nj = 0; nj < 8; nj++) {
                const int col = wn * 64 + nj * 8 + g;
                bf[nj][0] = *(const uint32_t*)&Bb[col * SKP + kb];
                bf[nj][1] = *(const uint32_t*)&Bb[col * SKP + kb + 8];
            }
            #pragma unroll
            for (int mi = 0; mi < 2; mi++)
                #pragma unroll
                for (int nj = 0; nj < 8; nj++)
                    mma_f16(acc[mi][nj], af[mi], bf[nj]);
        }
    }

    // epilogue
    #pragma unroll
    for (int mi = 0; mi < 2; mi++) {
        #pragma unroll
        for (int nj = 0; nj < 8; nj++) {
            const int col = n0 + wn * 64 + nj * 8 + tig * 2;
            const float b0 = bias[col], b1 = bias[col + 1];
            #pragma unroll
            for (int h = 0; h < 2; h++) {
                const int row = m0 + wm * 32 + mi * 16 + g + h * 8;
                float v0 = acc[mi][nj][h * 2 + 0] + b0;
                float v1 = acc[mi][nj][h * 2 + 1] + b1;
                if (extra) {
                    const float* ex = extra + (size_t)(row >> 6) * N;
                    v0 += ex[col]; v1 += ex[col + 1];
                }
                *(float2*)&C[(size_t)row * N + col] = make_float2(v0, v1);
            }
        }
    }
}

// ---------------- segment attention (S=64), fp16 output ---------------------
template <int HD, int NH>
__global__ void __launch_bounds__(256) attn_kernel(const float* __restrict__ qkv,
                                                   __half* __restrict__ out) {
    constexpr int D  = NH * HD;
    constexpr int RS = 3 * D;
    constexpr int PS = HD + 1;
    constexpr int SP = 65;
    constexpr int TC = HD / 16;

    extern __shared__ float sm[];
    float* Qs = sm;
    float* Ks = sm + 64 * PS;
    float* Ss = sm + 2 * 64 * PS;

    const int tid = threadIdx.x;
    const int tx = tid & 15, ty = tid >> 4;
    const int seq = blockIdx.x;
    const int h = blockIdx.y;
    const float* base = qkv + (size_t)seq * 64 * RS;
    const int qoff = h * HD;
    const int koff = D + h * HD;
    const int voff = 2 * D + h * HD;

    for (int idx = tid * 4; idx < 64 * HD; idx += 1024) {
        const int s = idx / HD, d = idx - s * HD;
        const float* rp = base + (size_t)s * RS;
        float4 q4 = *(const float4*)(rp + qoff + d);
        float4 k4 = *(const float4*)(rp + koff + d);
        float* qd = &Qs[s * PS + d];
        qd[0] = q4.x; qd[1] = q4.y; qd[2] = q4.z; qd[3] = q4.w;
        float* kd = &Ks[s * PS + d];
        kd[0] = k4.x; kd[1] = k4.y; kd[2] = k4.z; kd[3] = k4.w;
    }
    __syncthreads();

    float acc[4][4] = {};
    #pragma unroll 4
    for (int k = 0; k < HD; k++) {
        float a[4], b[4];
        #pragma unroll
        for (int i = 0; i < 4; i++) a[i] = Qs[(ty * 4 + i) * PS + k];
        #pragma unroll
        for (int j = 0; j < 4; j++) b[j] = Ks[(tx * 4 + j) * PS + k];
        #pragma unroll
        for (int i = 0; i < 4; i++)
            #pragma unroll
            for (int j = 0; j < 4; j++)
                acc[i][j] += a[i] * b[j];
    }
    const float scale = rsqrtf((float)HD);
    #pragma unroll
    for (int i = 0; i < 4; i++)
        #pragma unroll
        for (int j = 0; j < 4; j++)
            Ss[(ty * 4 + i) * SP + tx * 4 + j] = acc[i][j] * scale;
    __syncthreads();

    if (tid < 64) {
        float* row = &Ss[tid * SP];
        float mx = -1e30f;
        for (int j = 0; j < 64; j++) mx = fmaxf(mx, row[j]);
        float sum = 0.f;
        for (int j = 0; j < 64; j++) { float e = expf(row[j] - mx); row[j] = e; sum += e; }
        const float inv = 1.0f / sum;
        for (int j = 0; j < 64; j++) row[j] *= inv;
    }
    __syncthreads();

    for (int idx = tid * 4; idx < 64 * HD; idx += 1024) {
        const int s = idx / HD, d = idx - s * HD;
        float4 v4 = *(const float4*)(base + (size_t)s * RS + voff + d);
        float* kd = &Ks[s * PS + d];
        kd[0] = v4.x; kd[1] = v4.y; kd[2] = v4.z; kd[3] = v4.w;
    }
    __syncthreads();

    float acc2[4][TC] = {};
    for (int j = 0; j < 64; j++) {
        float p[4];
        #pragma unroll
        for (int i = 0; i < 4; i++) p[i] = Ss[(ty * 4 + i) * SP + j];
        #pragma unroll
        for (int c = 0; c < TC; c++) {
            const float v = Ks[j * PS + tx * TC + c];
            #pragma unroll
            for (int i = 0; i < 4; i++) acc2[i][c] += p[i] * v;
        }
    }
    #pragma unroll
    for (int i = 0; i < 4; i++) {
        __half* op = out + (size_t)(seq * 64 + ty * 4 + i) * D + h * HD + tx * TC;
        #pragma unroll
        for (int c = 0; c < TC; c++) op[c] = __float2half_rn(acc2[i][c]);
    }
}

static const int SMEM_L = (2 * 64 * 129 + 64 * 65) * sizeof(float);
static const int SMEM_G = (2 * 64 * 257 + 64 * 65) * sizeof(float);

extern "C" void kernel_launch(void* const* d_in, const int* in_sizes, int n_in,
                              void* d_out, int out_size) {
    const float* x       = (const float*)d_in[0];
    const float* w_in_l  = (const float*)d_in[1];
    const float* b_in_l  = (const float*)d_in[2];
    const float* w_out_l = (const float*)d_in[3];
    const float* b_out_l = (const float*)d_in[4];
    const float* w_in_g  = (const float*)d_in[5];
    const float* b_in_g  = (const float*)d_in[6];
    const float* w_out_g = (const float*)d_in[7];
    const float* b_out_g = (const float*)d_in[8];
    float* out = (float*)d_out;

    __half *xh, *w1l, *w2l, *w1g, *w2g, *lattn, *means, *gattn;
    float *qkv_l, *qkv_g, *glob;
    cudaGetSymbolAddress((void**)&xh,    g_xh);
    cudaGetSymbolAddress((void**)&w1l,   g_w1l_h);
    cudaGetSymbolAddress((void**)&w2l,   g_w2l_h);
    cudaGetSymbolAddress((void**)&w1g,   g_w1g_h);
    cudaGetSymbolAddress((void**)&w2g,   g_w2g_h);
    cudaGetSymbolAddress((void**)&qkv_l, g_qkv_l);
    cudaGetSymbolAddress((void**)&lattn, g_lattn);
    cudaGetSymbolAddress((void**)&means, g_means);
    cudaGetSymbolAddress((void**)&qkv_g, g_qkv_g);
    cudaGetSymbolAddress((void**)&gattn, g_gattn);
    cudaGetSymbolAddress((void**)&glob,  g_glob);

    cudaFuncSetAttribute((const void*)gemm_h,
                         cudaFuncAttributeMaxDynamicSharedMemorySize, GEMM_DYN_SMEM);
    cudaFuncSetAttribute((const void*)attn_kernel<128, 8>,
                         cudaFuncAttributeMaxDynamicSharedMemorySize, SMEM_L);
    cudaFuncSetAttribute((const void*)attn_kernel<256, 4>,
                         cudaFuncAttributeMaxDynamicSharedMemorySize, SMEM_G);

    // ---- fp16 conversions ----
    {
        int n4 = M_LOC * DIM / 4;
        f2h_kernel<<<(n4 + 255) / 256, 256>>>((const float4*)x, (__half2*)xh, n4);
        n4 = QKVDIM * DIM / 4;
        f2h_kernel<<<(n4 + 255) / 256, 256>>>((const float4*)w_in_l, (__half2*)w1l, n4);
        f2h_kernel<<<(n4 + 255) / 256, 256>>>((const float4*)w_in_g, (__half2*)w1g, n4);
        n4 = DIM * DIM / 4;
        f2h_kernel<<<(n4 + 255) / 256, 256>>>((const float4*)w_out_l, (__half2*)w2l, n4);
        f2h_kernel<<<(n4 + 255) / 256, 256>>>((const float4*)w_out_g, (__half2*)w2g, n4);
    }

    // ---- global path (tiny) ----
    means_kernel<<<M_GLB, 256>>>(x, means);
    gemm_h<<<dim3(QKVDIM / BN, M_GLB / BM), 256, GEMM_DYN_SMEM>>>(
        means, w1g, b_in_g, nullptr, qkv_g, M_GLB, QKVDIM, DIM);
    attn_kernel<256, 4><<<dim3(4, 4), 256, SMEM_G>>>(qkv_g, gattn);
    gemm_h<<<dim3(DIM / BN, M_GLB / BM), 256, GEMM_DYN_SMEM>>>(
        gattn, w2g, b_out_g, nullptr, glob, M_GLB, DIM, DIM);

    // ---- local path (bulk of FLOPs) ----
    gemm_h<<<dim3(QKVDIM / BN, M_LOC / BM), 256, GEMM_DYN_SMEM>>>(
        xh, w1l, b_in_l, nullptr, qkv_l, M_LOC, QKVDIM, DIM);
    attn_kernel<128, 8><<<dim3(M_GLB, 8), 256, SMEM_L>>>(qkv_l, lattn);
    gemm_h<<<dim3(DIM / BN, M_LOC / BM), 256, GEMM_DYN_SMEM>>>(
        lattn, w2l, b_out_l, glob, out, M_LOC, DIM, DIM);
}